// round 15
// baseline (speedup 1.0000x reference)
#include <cuda_runtime.h>
#include <cstdint>

typedef unsigned long long u64;

#define NQ   4
#define PROJ 64
#define TPB  256
#define WARPS (TPB/32)
#define GRID 592

// ---------------- f32x2 helpers (Blackwell packed fp32) ----------------
__device__ __forceinline__ u64 pk(float lo, float hi) {
    u64 r; asm("mov.b64 %0, {%1, %2};" : "=l"(r) : "f"(lo), "f"(hi)); return r;
}
__device__ __forceinline__ float2 upk(u64 v) {
    float2 r; asm("mov.b64 {%0, %1}, %2;" : "=f"(r.x), "=f"(r.y) : "l"(v)); return r;
}
__device__ __forceinline__ u64 fma2(u64 a, u64 b, u64 c) {
    u64 d; asm("fma.rn.f32x2 %0, %1, %2, %3;" : "=l"(d) : "l"(a), "l"(b), "l"(c)); return d;
}
__device__ __forceinline__ u64 mul2(u64 a, u64 b) {
    u64 d; asm("mul.rn.f32x2 %0, %1, %2;" : "=l"(d) : "l"(a), "l"(b)); return d;
}
__device__ __forceinline__ float tanh_hw(float v) {
    float r; asm("tanh.approx.f32 %0, %1;" : "=f"(r) : "f"(v)); return r;
}

// ---------------- single fused kernel ----------------
__global__ void __launch_bounds__(TPB, 4)
quantum_kernel(const float* __restrict__ x,
               const float* __restrict__ weights,
               const float* __restrict__ W,
               const float* __restrict__ b,
               const float* __restrict__ gamma,
               const float* __restrict__ beta,
               float* __restrict__ out, int Bn)
{
    __shared__ float2 sM[8][4];
    __shared__ float sVr[16][16];
    __shared__ float sVi[16][16];
    __shared__ float sgc[32];
    __shared__ __align__(16) u64 bufA[512];       // S in pair-radix layout
    __shared__ __align__(16) ulonglong2 sC[81];
    // packed LN constants: [0..3]={A0j,A1j}, [4..7]={A2j,A3j},
    // [8]={2u0,2u1}, [9]={2u2,2u3}, [10]={wb0,wb1}, [11]={wb2,wb3}, [12]={e,bbar}
    __shared__ __align__(16) u64 sK2[13];
    __shared__ __align__(16) ulonglong2 sPC[16][5];
    __shared__ __align__(16) u64 s_q[WARPS][32][4];

    const int tid  = threadIdx.x;
    const int lane = tid & 31;
    const int wid  = tid >> 5;

    // ================= PROLOGUE (identical in every block) =================
    float4 wr0, wr1; float br0 = 0.f, br1 = 0.f;
    if (tid >= 32 && tid < 64) {
        int ln = tid - 32;
        wr0 = *(const float4*)(W + ln * 4);
        br0 = b[ln];
        wr1 = *(const float4*)(W + (ln + 32) * 4);
        br1 = b[ln + 32];
    }

    if (tid < 8) {
        int l = tid >> 2, w = tid & 3;
        float phi = weights[l * 12 + w * 3 + 0];
        float th  = weights[l * 12 + w * 3 + 1];
        float om  = weights[l * 12 + w * 3 + 2];
        float c, s; __sincosf(0.5f * th, &s, &c);
        float ap = -0.5f * (phi + om);
        float am =  0.5f * (phi - om);
        float cap, sap, cam, sam;
        __sincosf(ap, &sap, &cap);
        __sincosf(am, &sam, &cam);
        sM[tid][0] = make_float2( c * cap,  c * sap);
        sM[tid][1] = make_float2(-s * cam, -s * sam);
        sM[tid][2] = make_float2( s * cam, -s * sam);
        sM[tid][3] = make_float2( c * cap, -c * sap);
    }
    __syncthreads();

    // V build, shuffle-parallel: thread = (column vj, amplitude vo).
    {
        const int vj = tid >> 4;
        const int vo = tid & 15;
        float ar = (vo == vj) ? 1.f : 0.f;
        float ai = 0.f;
        #pragma unroll
        for (int l = 0; l < 2; l++) {
            #pragma unroll
            for (int w = 0; w < NQ; w++) {
                int g = l * 4 + w;
                int m = 8 >> w;
                float2 M00 = sM[g][0], M01 = sM[g][1], M10 = sM[g][2], M11 = sM[g][3];
                float apr = __shfl_xor_sync(0xffffffffu, ar, m);
                float api = __shfl_xor_sync(0xffffffffu, ai, m);
                bool hi = (vo & m) != 0;
                float2 Cs = hi ? M11 : M00;
                float2 Cp = hi ? M10 : M01;
                float nr = Cs.x*ar - Cs.y*ai + Cp.x*apr - Cp.y*api;
                float ni = Cs.x*ai + Cs.y*ar + Cp.x*api + Cp.y*apr;
                ar = nr; ai = ni;
            }
            int rr = (l % 3) + 1;
            #pragma unroll
            for (int w = 0; w < NQ; w++) {
                int cm = 8 >> w, tm = 8 >> ((w + rr) & 3);
                float apr = __shfl_xor_sync(0xffffffffu, ar, tm);
                float api = __shfl_xor_sync(0xffffffffu, ai, tm);
                if (vo & cm) { ar = apr; ai = api; }
            }
        }
        int pc = __popc(vj) & 3;
        float fr = (pc == 0) ? 1.f : ((pc == 2) ? -1.f : 0.f);
        float fi = (pc == 1) ? -1.f : ((pc == 3) ? 1.f : 0.f);
        sVr[vo][vj] = ar * fr - ai * fi;
        sVi[vo][vj] = ar * fi + ai * fr;
    }

    // warp 1: projection / LN constants (register data, shuffle reduction)
    if (tid >= 32 && tid < 64) {
        int ln = tid - 32;
        float A[16], u4[4], wb[4], e = 0.f, bb = 0.f;
        #pragma unroll
        for (int i = 0; i < 16; i++) A[i] = 0.f;
        #pragma unroll
        for (int i = 0; i < 4; i++) { u4[i] = 0.f; wb[i] = 0.f; }
        #pragma unroll
        for (int rep = 0; rep < 2; rep++) {
            float4 wr = rep ? wr1 : wr0;
            float br  = rep ? br1 : br0;
            float wv[4] = {wr.x, wr.y, wr.z, wr.w};
            #pragma unroll
            for (int i = 0; i < 4; i++) {
                #pragma unroll
                for (int jj = 0; jj < 4; jj++) A[i * 4 + jj] += wv[i] * wv[jj];
                u4[i] += wv[i] * br;
                wb[i] += wv[i];
            }
            e += br * br; bb += br;
        }
        #pragma unroll
        for (int off = 16; off > 0; off >>= 1) {
            #pragma unroll
            for (int i = 0; i < 16; i++) A[i] += __shfl_xor_sync(0xffffffffu, A[i], off);
            #pragma unroll
            for (int i = 0; i < 4; i++) {
                u4[i] += __shfl_xor_sync(0xffffffffu, u4[i], off);
                wb[i] += __shfl_xor_sync(0xffffffffu, wb[i], off);
            }
            e  += __shfl_xor_sync(0xffffffffu, e, off);
            bb += __shfl_xor_sync(0xffffffffu, bb, off);
        }
        if (ln == 0) {
            const float inv = 1.f / 64.f;
            #pragma unroll
            for (int i = 0; i < 16; i++) sgc[i] = A[i] * inv;
            #pragma unroll
            for (int i = 0; i < 4; i++) {
                sgc[16 + i] = u4[i] * inv;
                sgc[21 + i] = wb[i] * inv;
            }
            sgc[20] = e * inv;
            sgc[25] = bb * inv;
        }
    }
    __syncthreads();

    // S_w[j][k] -> pair-radix layout in bufA
    {
        int j = tid >> 4, k = tid & 15;
        float a0 = 0.f, a1 = 0.f, a2 = 0.f, a3 = 0.f;
        #pragma unroll
        for (int o = 0; o < 16; o++) {
            float d = sVr[o][j] * sVr[o][k] + sVi[o][j] * sVi[o][k];
            a0 += (o & 8) ? -d : d;
            a1 += (o & 4) ? -d : d;
            a2 += (o & 2) ? -d : d;
            a3 += (o & 1) ? -d : d;
        }
        int p0 = 2 * ((j >> 3) & 1) + ((k >> 3) & 1);
        int p1 = 2 * ((j >> 2) & 1) + ((k >> 2) & 1);
        int p2 = 2 * ((j >> 1) & 1) + ((k >> 1) & 1);
        int p3 = 2 * (j & 1) + (k & 1);
        int idx = ((p0 * 4 + p1) * 4 + p2) * 4 + p3;
        bufA[idx * 2 + 0] = pk(a0, a1);
        bufA[idx * 2 + 1] = pk(a2, a3);
    }
    __syncthreads();

    // ---- single-stage C gather: one thread per output (t, pack) ----
    if (tid < 162) {
        int pack = tid & 1, t = tid >> 1;
        int e0 = t % 3, e1 = (t / 3) % 3, e2 = (t / 9) % 3, e3 = t / 27;
        int a0 = (e0 == 2) ? 1*128 : 0,  b0v = (e0 == 2) ? 2*128 : 3*128;
        int a1 = (e1 == 2) ? 1*32  : 0,  b1v = (e1 == 2) ? 2*32  : 3*32;
        int a2 = (e2 == 2) ? 1*8   : 0,  b2v = (e2 == 2) ? 2*8   : 3*8;
        int a3 = (e3 == 2) ? 1*2   : 0,  b3v = (e3 == 2) ? 2*2   : 3*2;
        int m1 = (e0 == 1 ? 1 : 0) | (e1 == 1 ? 2 : 0) | (e2 == 1 ? 4 : 0) | (e3 == 1 ? 8 : 0);
        float sx = 0.f, sy = 0.f;
        #pragma unroll
        for (int c = 0; c < 16; c++) {
            int idx2 = ((c & 1) ? b0v : a0) + ((c & 2) ? b1v : a1)
                     + ((c & 4) ? b2v : a2) + ((c & 8) ? b3v : a3) + pack;
            float2 f = upk(bufA[idx2]);
            if (__popc(c & m1) & 1) { sx -= f.x; sy -= f.y; }
            else                    { sx += f.x; sy += f.y; }
        }
        ((u64*)sC)[t * 2 + pack] = pk(sx * 0.0625f, sy * 0.0625f);
    }
    if (tid >= 192 && tid < 208) {   // sPC: folded projection table, 4 cols per entry
        int g = tid - 192;
        float bb = sgc[25];
        u64 Gl[4], Gh[4];
        #pragma unroll
        for (int h = 0; h < 2; h++) {
            int j0 = 4 * g + 2 * h, j1 = j0 + 1;
            float b0 = b[j0], b1 = b[j1];
            float g0 = gamma[j0], g1 = gamma[j1];
            #pragma unroll
            for (int i = 0; i < 4; i++) {
                float wb = sgc[21 + i];
                float w0 = W[j0 * 4 + i] - wb + b0 - bb;
                float w1 = W[j1 * 4 + i] - wb + b1 - bb;
                if (h == 0) Gl[i] = pk(g0 * w0, g1 * w1);
                else        Gh[i] = pk(g0 * w0, g1 * w1);
            }
        }
        sPC[g][0] = make_ulonglong2(Gl[0], Gl[1]);
        sPC[g][1] = make_ulonglong2(Gl[2], Gl[3]);
        sPC[g][2] = make_ulonglong2(Gh[0], Gh[1]);
        sPC[g][3] = make_ulonglong2(Gh[2], Gh[3]);
        sPC[g][4] = make_ulonglong2(pk(beta[4*g], beta[4*g+1]), pk(beta[4*g+2], beta[4*g+3]));
    }
    if (tid >= 224 && tid < 237) {   // packed LN constants
        int i = tid - 224;
        u64 v;
        if (i < 4)       v = pk(sgc[0 * 4 + i], sgc[1 * 4 + i]);
        else if (i < 8)  v = pk(sgc[2 * 4 + (i - 4)], sgc[3 * 4 + (i - 4)]);
        else if (i == 8) v = pk(2.f * sgc[16], 2.f * sgc[17]);
        else if (i == 9) v = pk(2.f * sgc[18], 2.f * sgc[19]);
        else if (i == 10) v = pk(sgc[21], sgc[22]);
        else if (i == 11) v = pk(sgc[23], sgc[24]);
        else              v = pk(sgc[20], sgc[25]);
        sK2[i] = v;
    }
    __syncthreads();

    // ================= MAIN LOOP =================
    const int g4 = lane & 15;
    const int p  = lane >> 4;
    const int jcol = 4 * g4;
    float2 EB = upk(sK2[12]);    // e, bbar

    const int warp_global = blockIdx.x * WARPS + wid;
    const int nwarps  = GRID * WARPS;
    const int nchunks = Bn >> 5;

    for (int chunk = warp_global; chunk < nchunks; chunk += nwarps) {
        const int base = chunk << 5;
        const int s = base + lane;

        // ---- phase 1: one sample per lane ----
        float4 xv = *(const float4*)(x + (size_t)s * 4);
        float xs[4] = {xv.x, xv.y, xv.z, xv.w};
        u64 cp[4], sp[4];
        #pragma unroll
        for (int w = 0; w < 4; w++) {
            float th = tanh_hw(xs[w]);                        // HW tanh (MUFU)
            float sn, cs;
            __sincosf(3.14159265358979323846f * th, &sn, &cs);
            cp[w] = pk(cs, cs);
            sp[w] = pk(sn, sn);
        }

        // z = sum_e C[e] * prod_w (1,cos,sin)_{e_w}
        u64 z01 = 0ull, z23 = 0ull;
        #pragma unroll
        for (int e3 = 0; e3 < 3; e3++) {
            u64 a3_01, a3_23;
            #pragma unroll
            for (int e2 = 0; e2 < 3; e2++) {
                u64 a2_01, a2_23;
                #pragma unroll
                for (int e1 = 0; e1 < 3; e1++) {
                    int cbase = ((e3 * 3 + e2) * 3 + e1) * 3;
                    ulonglong2 C0 = sC[cbase];
                    ulonglong2 C1 = sC[cbase + 1];
                    ulonglong2 C2 = sC[cbase + 2];
                    u64 t01 = fma2(cp[0], C1.x, C0.x); t01 = fma2(sp[0], C2.x, t01);
                    u64 t23 = fma2(cp[0], C1.y, C0.y); t23 = fma2(sp[0], C2.y, t23);
                    if (e1 == 0)      { a2_01 = t01;                   a2_23 = t23; }
                    else if (e1 == 1) { a2_01 = fma2(cp[1], t01, a2_01); a2_23 = fma2(cp[1], t23, a2_23); }
                    else              { a2_01 = fma2(sp[1], t01, a2_01); a2_23 = fma2(sp[1], t23, a2_23); }
                }
                if (e2 == 0)      { a3_01 = a2_01;                    a3_23 = a2_23; }
                else if (e2 == 1) { a3_01 = fma2(cp[2], a2_01, a3_01); a3_23 = fma2(cp[2], a2_23, a3_23); }
                else              { a3_01 = fma2(sp[2], a2_01, a3_01); a3_23 = fma2(sp[2], a2_23, a3_23); }
            }
            if (e3 == 0)      { z01 = a3_01;                    z23 = a3_23; }
            else if (e3 == 1) { z01 = fma2(cp[3], a3_01, z01);  z23 = fma2(cp[3], a3_23, z23); }
            else              { z01 = fma2(sp[3], a3_01, z01);  z23 = fma2(sp[3], a3_23, z23); }
        }
        float2 zA = upk(z01), zB = upk(z23);

        // softmax (z in [-1,1], no max-shift needed)
        float q0 = __expf(zA.x), q1 = __expf(zA.y), q2 = __expf(zB.x), q3 = __expf(zB.y);
        float inv = __fdividef(1.f, (q0 + q1) + (q2 + q3));
        q0 *= inv; q1 *= inv; q2 *= inv; q3 *= inv;

        u64 qb0 = pk(q0, q0), qb1 = pk(q1, q1), qb2 = pk(q2, q2), qb3 = pk(q3, q3);
        u64 q01 = pk(q0, q1), q23 = pk(q2, q3);

        // LN stats via packed quadratic forms
        u64 m2 = fma2(sK2[10], q01, mul2(sK2[11], q23));
        float2 M = upk(m2);
        float mu = EB.y + M.x + M.y;
        u64 ti01 = sK2[8];
        ti01 = fma2(sK2[0], qb0, ti01);
        ti01 = fma2(sK2[1], qb1, ti01);
        ti01 = fma2(sK2[2], qb2, ti01);
        ti01 = fma2(sK2[3], qb3, ti01);
        u64 ti23 = sK2[9];
        ti23 = fma2(sK2[4], qb0, ti23);
        ti23 = fma2(sK2[5], qb1, ti23);
        ti23 = fma2(sK2[6], qb2, ti23);
        ti23 = fma2(sK2[7], qb3, ti23);
        u64 ehp = fma2(ti01, q01, mul2(ti23, q23));
        float2 E2 = upk(ehp);
        float eh2 = EB.x + E2.x + E2.y;
        float var = fmaf(-mu, mu, eh2);
        float rs = rsqrtf(var + 1e-5f);

        // store rs-scaled q, replicated {v,v}
        {
            u64 rs2 = pk(rs, rs);
            ulonglong2* dst = (ulonglong2*)&s_q[wid][lane][0];
            dst[0] = make_ulonglong2(mul2(qb0, rs2), mul2(qb1, rs2));
            dst[1] = make_ulonglong2(mul2(qb2, rs2), mul2(qb3, rs2));
        }
        __syncwarp();

        // ---- phase 2: half-warp per row, 4 cols/lane, STG.128 ----
        // constants loaded from smem per chunk (keeps live registers under
        // the 64-reg occupancy-4 cap; broadcast LDS.128, cheap)
        {
            ulonglong2 A0 = sPC[g4][0], A1 = sPC[g4][1];
            ulonglong2 B0 = sPC[g4][2], B1 = sPC[g4][3];
            ulonglong2 BB = sPC[g4][4];
            #pragma unroll 4
            for (int r = 0; r < 16; r++) {
                const int row = 2 * r + p;
                const ulonglong2* qp = (const ulonglong2*)&s_q[wid][row][0];
                ulonglong2 qa2 = qp[0], qb2v = qp[1];
                u64 acc_lo = fma2(A0.x, qa2.x, BB.x);
                u64 acc_hi = fma2(B0.x, qa2.x, BB.y);
                acc_lo = fma2(A0.y, qa2.y, acc_lo);
                acc_hi = fma2(B0.y, qa2.y, acc_hi);
                acc_lo = fma2(A1.x, qb2v.x, acc_lo);
                acc_hi = fma2(B1.x, qb2v.x, acc_hi);
                acc_lo = fma2(A1.y, qb2v.y, acc_lo);
                acc_hi = fma2(B1.y, qb2v.y, acc_hi);
                float2 lo = upk(acc_lo), hi = upk(acc_hi);
                float4 ov = make_float4(lo.x, lo.y, hi.x, hi.y);
                *(float4*)(out + (size_t)(base + row) * PROJ + jcol) = ov;
            }
        }
        __syncwarp();
    }
}

extern "C" void kernel_launch(void* const* d_in, const int* in_sizes, int n_in,
                              void* d_out, int out_size)
{
    const float* x       = (const float*)d_in[0];
    const float* weights = (const float*)d_in[1];
    const float* W       = (const float*)d_in[2];
    const float* b       = (const float*)d_in[3];
    const float* gamma   = (const float*)d_in[4];
    const float* beta    = (const float*)d_in[5];
    float* out = (float*)d_out;
    int Bn = in_sizes[0] / NQ;

    quantum_kernel<<<GRID, TPB>>>(x, weights, W, b, gamma, beta, out, Bn);
}

// round 16
// speedup vs baseline: 1.1169x; 1.1169x over previous
#include <cuda_runtime.h>
#include <cstdint>

typedef unsigned long long u64;

#define NQ   4
#define PROJ 64
#define TPB  256
#define WARPS (TPB/32)
#define GRID 444

// ---------------- f32x2 helpers (Blackwell packed fp32) ----------------
__device__ __forceinline__ u64 pk(float lo, float hi) {
    u64 r; asm("mov.b64 %0, {%1, %2};" : "=l"(r) : "f"(lo), "f"(hi)); return r;
}
__device__ __forceinline__ float2 upk(u64 v) {
    float2 r; asm("mov.b64 {%0, %1}, %2;" : "=f"(r.x), "=f"(r.y) : "l"(v)); return r;
}
__device__ __forceinline__ u64 fma2(u64 a, u64 b, u64 c) {
    u64 d; asm("fma.rn.f32x2 %0, %1, %2, %3;" : "=l"(d) : "l"(a), "l"(b), "l"(c)); return d;
}
__device__ __forceinline__ u64 mul2(u64 a, u64 b) {
    u64 d; asm("mul.rn.f32x2 %0, %1, %2;" : "=l"(d) : "l"(a), "l"(b)); return d;
}

// ---------------- single fused kernel ----------------
__global__ void __launch_bounds__(TPB, 3)
quantum_kernel(const float* __restrict__ x,
               const float* __restrict__ weights,
               const float* __restrict__ W,
               const float* __restrict__ b,
               const float* __restrict__ gamma,
               const float* __restrict__ beta,
               float* __restrict__ out, int Bn)
{
    __shared__ float2 sM[8][4];
    __shared__ float sVr[16][16];
    __shared__ float sVi[16][16];
    __shared__ float sgc[32];
    __shared__ __align__(16) u64 bufA[512];       // S in pair-radix layout
    __shared__ __align__(16) ulonglong2 sC[81];
    // packed LN constants: [0..3]={A0j,A1j}, [4..7]={A2j,A3j},
    // [8]={2u0,2u1}, [9]={2u2,2u3}, [10]={wb0,wb1}, [11]={wb2,wb3}, [12]={e,bbar}
    __shared__ __align__(16) u64 sK2[13];
    __shared__ __align__(16) ulonglong2 sPC[16][5];
    __shared__ __align__(16) u64 s_q[WARPS][32][4];

    const int tid  = threadIdx.x;
    const int lane = tid & 31;
    const int wid  = tid >> 5;

    // ================= PROLOGUE (identical in every block) =================
    float4 wr0, wr1; float br0 = 0.f, br1 = 0.f;
    if (tid >= 32 && tid < 64) {
        int ln = tid - 32;
        wr0 = *(const float4*)(W + ln * 4);
        br0 = b[ln];
        wr1 = *(const float4*)(W + (ln + 32) * 4);
        br1 = b[ln + 32];
    }

    if (tid < 8) {
        int l = tid >> 2, w = tid & 3;
        float phi = weights[l * 12 + w * 3 + 0];
        float th  = weights[l * 12 + w * 3 + 1];
        float om  = weights[l * 12 + w * 3 + 2];
        float c, s; __sincosf(0.5f * th, &s, &c);
        float ap = -0.5f * (phi + om);
        float am =  0.5f * (phi - om);
        float cap, sap, cam, sam;
        __sincosf(ap, &sap, &cap);
        __sincosf(am, &sam, &cam);
        sM[tid][0] = make_float2( c * cap,  c * sap);
        sM[tid][1] = make_float2(-s * cam, -s * sam);
        sM[tid][2] = make_float2( s * cam, -s * sam);
        sM[tid][3] = make_float2( c * cap, -c * sap);
    }
    __syncthreads();

    // V build, shuffle-parallel: thread = (column vj, amplitude vo).
    {
        const int vj = tid >> 4;
        const int vo = tid & 15;
        float ar = (vo == vj) ? 1.f : 0.f;
        float ai = 0.f;
        #pragma unroll
        for (int l = 0; l < 2; l++) {
            #pragma unroll
            for (int w = 0; w < NQ; w++) {
                int g = l * 4 + w;
                int m = 8 >> w;
                float2 M00 = sM[g][0], M01 = sM[g][1], M10 = sM[g][2], M11 = sM[g][3];
                float apr = __shfl_xor_sync(0xffffffffu, ar, m);
                float api = __shfl_xor_sync(0xffffffffu, ai, m);
                bool hi = (vo & m) != 0;
                float2 Cs = hi ? M11 : M00;
                float2 Cp = hi ? M10 : M01;
                float nr = Cs.x*ar - Cs.y*ai + Cp.x*apr - Cp.y*api;
                float ni = Cs.x*ai + Cs.y*ar + Cp.x*api + Cp.y*apr;
                ar = nr; ai = ni;
            }
            int rr = (l % 3) + 1;
            #pragma unroll
            for (int w = 0; w < NQ; w++) {
                int cm = 8 >> w, tm = 8 >> ((w + rr) & 3);
                float apr = __shfl_xor_sync(0xffffffffu, ar, tm);
                float api = __shfl_xor_sync(0xffffffffu, ai, tm);
                if (vo & cm) { ar = apr; ai = api; }
            }
        }
        int pc = __popc(vj) & 3;
        float fr = (pc == 0) ? 1.f : ((pc == 2) ? -1.f : 0.f);
        float fi = (pc == 1) ? -1.f : ((pc == 3) ? 1.f : 0.f);
        sVr[vo][vj] = ar * fr - ai * fi;
        sVi[vo][vj] = ar * fi + ai * fr;
    }

    // warp 1: projection / LN constants (register data, shuffle reduction)
    if (tid >= 32 && tid < 64) {
        int ln = tid - 32;
        float A[16], u4[4], wb[4], e = 0.f, bb = 0.f;
        #pragma unroll
        for (int i = 0; i < 16; i++) A[i] = 0.f;
        #pragma unroll
        for (int i = 0; i < 4; i++) { u4[i] = 0.f; wb[i] = 0.f; }
        #pragma unroll
        for (int rep = 0; rep < 2; rep++) {
            float4 wr = rep ? wr1 : wr0;
            float br  = rep ? br1 : br0;
            float wv[4] = {wr.x, wr.y, wr.z, wr.w};
            #pragma unroll
            for (int i = 0; i < 4; i++) {
                #pragma unroll
                for (int jj = 0; jj < 4; jj++) A[i * 4 + jj] += wv[i] * wv[jj];
                u4[i] += wv[i] * br;
                wb[i] += wv[i];
            }
            e += br * br; bb += br;
        }
        #pragma unroll
        for (int off = 16; off > 0; off >>= 1) {
            #pragma unroll
            for (int i = 0; i < 16; i++) A[i] += __shfl_xor_sync(0xffffffffu, A[i], off);
            #pragma unroll
            for (int i = 0; i < 4; i++) {
                u4[i] += __shfl_xor_sync(0xffffffffu, u4[i], off);
                wb[i] += __shfl_xor_sync(0xffffffffu, wb[i], off);
            }
            e  += __shfl_xor_sync(0xffffffffu, e, off);
            bb += __shfl_xor_sync(0xffffffffu, bb, off);
        }
        if (ln == 0) {
            const float inv = 1.f / 64.f;
            #pragma unroll
            for (int i = 0; i < 16; i++) sgc[i] = A[i] * inv;
            #pragma unroll
            for (int i = 0; i < 4; i++) {
                sgc[16 + i] = u4[i] * inv;
                sgc[21 + i] = wb[i] * inv;
            }
            sgc[20] = e * inv;
            sgc[25] = bb * inv;
        }
    }
    __syncthreads();

    // S_w[j][k] -> pair-radix layout in bufA
    {
        int j = tid >> 4, k = tid & 15;
        float a0 = 0.f, a1 = 0.f, a2 = 0.f, a3 = 0.f;
        #pragma unroll
        for (int o = 0; o < 16; o++) {
            float d = sVr[o][j] * sVr[o][k] + sVi[o][j] * sVi[o][k];
            a0 += (o & 8) ? -d : d;
            a1 += (o & 4) ? -d : d;
            a2 += (o & 2) ? -d : d;
            a3 += (o & 1) ? -d : d;
        }
        int p0 = 2 * ((j >> 3) & 1) + ((k >> 3) & 1);
        int p1 = 2 * ((j >> 2) & 1) + ((k >> 2) & 1);
        int p2 = 2 * ((j >> 1) & 1) + ((k >> 1) & 1);
        int p3 = 2 * (j & 1) + (k & 1);
        int idx = ((p0 * 4 + p1) * 4 + p2) * 4 + p3;
        bufA[idx * 2 + 0] = pk(a0, a1);
        bufA[idx * 2 + 1] = pk(a2, a3);
    }
    __syncthreads();

    // ---- single-stage C gather: one thread per output (t, pack) ----
    if (tid < 162) {
        int pack = tid & 1, t = tid >> 1;
        int e0 = t % 3, e1 = (t / 3) % 3, e2 = (t / 9) % 3, e3 = t / 27;
        int a0 = (e0 == 2) ? 1*128 : 0,  b0v = (e0 == 2) ? 2*128 : 3*128;
        int a1 = (e1 == 2) ? 1*32  : 0,  b1v = (e1 == 2) ? 2*32  : 3*32;
        int a2 = (e2 == 2) ? 1*8   : 0,  b2v = (e2 == 2) ? 2*8   : 3*8;
        int a3 = (e3 == 2) ? 1*2   : 0,  b3v = (e3 == 2) ? 2*2   : 3*2;
        int m1 = (e0 == 1 ? 1 : 0) | (e1 == 1 ? 2 : 0) | (e2 == 1 ? 4 : 0) | (e3 == 1 ? 8 : 0);
        float sx = 0.f, sy = 0.f;
        #pragma unroll
        for (int c = 0; c < 16; c++) {
            int idx2 = ((c & 1) ? b0v : a0) + ((c & 2) ? b1v : a1)
                     + ((c & 4) ? b2v : a2) + ((c & 8) ? b3v : a3) + pack;
            float2 f = upk(bufA[idx2]);
            if (__popc(c & m1) & 1) { sx -= f.x; sy -= f.y; }
            else                    { sx += f.x; sy += f.y; }
        }
        ((u64*)sC)[t * 2 + pack] = pk(sx * 0.0625f, sy * 0.0625f);
    }
    if (tid >= 192 && tid < 208) {   // sPC: folded projection table, 4 cols per entry
        int g = tid - 192;
        float bb = sgc[25];
        u64 Gl[4], Gh[4];
        #pragma unroll
        for (int h = 0; h < 2; h++) {
            int j0 = 4 * g + 2 * h, j1 = j0 + 1;
            float b0 = b[j0], b1 = b[j1];
            float g0 = gamma[j0], g1 = gamma[j1];
            #pragma unroll
            for (int i = 0; i < 4; i++) {
                float wb = sgc[21 + i];
                float w0 = W[j0 * 4 + i] - wb + b0 - bb;
                float w1 = W[j1 * 4 + i] - wb + b1 - bb;
                if (h == 0) Gl[i] = pk(g0 * w0, g1 * w1);
                else        Gh[i] = pk(g0 * w0, g1 * w1);
            }
        }
        sPC[g][0] = make_ulonglong2(Gl[0], Gl[1]);
        sPC[g][1] = make_ulonglong2(Gl[2], Gl[3]);
        sPC[g][2] = make_ulonglong2(Gh[0], Gh[1]);
        sPC[g][3] = make_ulonglong2(Gh[2], Gh[3]);
        sPC[g][4] = make_ulonglong2(pk(beta[4*g], beta[4*g+1]), pk(beta[4*g+2], beta[4*g+3]));
    }
    if (tid >= 224 && tid < 237) {   // packed LN constants
        int i = tid - 224;
        u64 v;
        if (i < 4)       v = pk(sgc[0 * 4 + i], sgc[1 * 4 + i]);
        else if (i < 8)  v = pk(sgc[2 * 4 + (i - 4)], sgc[3 * 4 + (i - 4)]);
        else if (i == 8) v = pk(2.f * sgc[16], 2.f * sgc[17]);
        else if (i == 9) v = pk(2.f * sgc[18], 2.f * sgc[19]);
        else if (i == 10) v = pk(sgc[21], sgc[22]);
        else if (i == 11) v = pk(sgc[23], sgc[24]);
        else              v = pk(sgc[20], sgc[25]);
        sK2[i] = v;
    }
    __syncthreads();

    // ================= MAIN LOOP =================
    const int g4 = lane & 15;
    const int p  = lane >> 4;
    const int jcol = 4 * g4;

    ulonglong2 A0 = sPC[g4][0], A1 = sPC[g4][1];
    ulonglong2 B0 = sPC[g4][2], B1 = sPC[g4][3];
    ulonglong2 BB = sPC[g4][4];
    float2 EB = upk(sK2[12]);    // e, bbar

    const int warp_global = blockIdx.x * WARPS + wid;
    const int nwarps  = GRID * WARPS;
    const int nchunks = Bn >> 5;

    int chunk = warp_global;
    bool valid = chunk < nchunks;
    float4 xv;
    if (valid) xv = *(const float4*)(x + (((size_t)chunk << 5) + lane) * 4);

    while (valid) {
        const int base = chunk << 5;

        // prefetch next chunk's x — its ~600-cycle latency drains under the
        // contraction + phase 2 instead of heading the next iteration
        const int next = chunk + nwarps;
        const bool nvalid = next < nchunks;
        float4 xn;
        if (nvalid) xn = *(const float4*)(x + (((size_t)next << 5) + lane) * 4);

        // ---- phase 1: one sample per lane ----
        float xs[4] = {xv.x, xv.y, xv.z, xv.w};
        u64 cp[4], sp[4];
        #pragma unroll
        for (int w = 0; w < 4; w++) {
            float t  = __expf(xs[w] + xs[w]);
            float th = 1.f - __fdividef(2.f, t + 1.f);        // tanh
            float sn, cs;
            __sincosf(3.14159265358979323846f * th, &sn, &cs);
            cp[w] = pk(cs, cs);
            sp[w] = pk(sn, sn);
        }

        // z = sum_e C[e] * prod_w (1,cos,sin)_{e_w}
        u64 z01 = 0ull, z23 = 0ull;
        #pragma unroll
        for (int e3 = 0; e3 < 3; e3++) {
            u64 a3_01, a3_23;
            #pragma unroll
            for (int e2 = 0; e2 < 3; e2++) {
                u64 a2_01, a2_23;
                #pragma unroll
                for (int e1 = 0; e1 < 3; e1++) {
                    int cbase = ((e3 * 3 + e2) * 3 + e1) * 3;
                    ulonglong2 C0 = sC[cbase];
                    ulonglong2 C1 = sC[cbase + 1];
                    ulonglong2 C2 = sC[cbase + 2];
                    u64 t01 = fma2(cp[0], C1.x, C0.x); t01 = fma2(sp[0], C2.x, t01);
                    u64 t23 = fma2(cp[0], C1.y, C0.y); t23 = fma2(sp[0], C2.y, t23);
                    if (e1 == 0)      { a2_01 = t01;                   a2_23 = t23; }
                    else if (e1 == 1) { a2_01 = fma2(cp[1], t01, a2_01); a2_23 = fma2(cp[1], t23, a2_23); }
                    else              { a2_01 = fma2(sp[1], t01, a2_01); a2_23 = fma2(sp[1], t23, a2_23); }
                }
                if (e2 == 0)      { a3_01 = a2_01;                    a3_23 = a2_23; }
                else if (e2 == 1) { a3_01 = fma2(cp[2], a2_01, a3_01); a3_23 = fma2(cp[2], a2_23, a3_23); }
                else              { a3_01 = fma2(sp[2], a2_01, a3_01); a3_23 = fma2(sp[2], a2_23, a3_23); }
            }
            if (e3 == 0)      { z01 = a3_01;                    z23 = a3_23; }
            else if (e3 == 1) { z01 = fma2(cp[3], a3_01, z01);  z23 = fma2(cp[3], a3_23, z23); }
            else              { z01 = fma2(sp[3], a3_01, z01);  z23 = fma2(sp[3], a3_23, z23); }
        }
        float2 zA = upk(z01), zB = upk(z23);

        // softmax (z in [-1,1], no max-shift needed)
        float q0 = __expf(zA.x), q1 = __expf(zA.y), q2 = __expf(zB.x), q3 = __expf(zB.y);
        float inv = __fdividef(1.f, (q0 + q1) + (q2 + q3));
        q0 *= inv; q1 *= inv; q2 *= inv; q3 *= inv;

        u64 qb0 = pk(q0, q0), qb1 = pk(q1, q1), qb2 = pk(q2, q2), qb3 = pk(q3, q3);
        u64 q01 = pk(q0, q1), q23 = pk(q2, q3);

        // LN stats via packed quadratic forms
        u64 m2 = fma2(sK2[10], q01, mul2(sK2[11], q23));
        float2 M = upk(m2);
        float mu = EB.y + M.x + M.y;
        u64 ti01 = sK2[8];
        ti01 = fma2(sK2[0], qb0, ti01);
        ti01 = fma2(sK2[1], qb1, ti01);
        ti01 = fma2(sK2[2], qb2, ti01);
        ti01 = fma2(sK2[3], qb3, ti01);
        u64 ti23 = sK2[9];
        ti23 = fma2(sK2[4], qb0, ti23);
        ti23 = fma2(sK2[5], qb1, ti23);
        ti23 = fma2(sK2[6], qb2, ti23);
        ti23 = fma2(sK2[7], qb3, ti23);
        u64 ehp = fma2(ti01, q01, mul2(ti23, q23));
        float2 E2 = upk(ehp);
        float eh2 = EB.x + E2.x + E2.y;
        float var = fmaf(-mu, mu, eh2);
        float rs = rsqrtf(var + 1e-5f);

        // store rs-scaled q, replicated {v,v}
        {
            u64 rs2 = pk(rs, rs);
            ulonglong2* dst = (ulonglong2*)&s_q[wid][lane][0];
            dst[0] = make_ulonglong2(mul2(qb0, rs2), mul2(qb1, rs2));
            dst[1] = make_ulonglong2(mul2(qb2, rs2), mul2(qb3, rs2));
        }
        __syncwarp();

        // ---- phase 2: half-warp per row, 4 cols/lane, STG.128 ----
        #pragma unroll 4
        for (int r = 0; r < 16; r++) {
            const int row = 2 * r + p;
            const ulonglong2* qp = (const ulonglong2*)&s_q[wid][row][0];
            ulonglong2 qa2 = qp[0], qb2v = qp[1];
            u64 acc_lo = fma2(A0.x, qa2.x, BB.x);
            u64 acc_hi = fma2(B0.x, qa2.x, BB.y);
            acc_lo = fma2(A0.y, qa2.y, acc_lo);
            acc_hi = fma2(B0.y, qa2.y, acc_hi);
            acc_lo = fma2(A1.x, qb2v.x, acc_lo);
            acc_hi = fma2(B1.x, qb2v.x, acc_hi);
            acc_lo = fma2(A1.y, qb2v.y, acc_lo);
            acc_hi = fma2(B1.y, qb2v.y, acc_hi);
            float2 lo = upk(acc_lo), hi = upk(acc_hi);
            float4 ov = make_float4(lo.x, lo.y, hi.x, hi.y);
            *(float4*)(out + (size_t)(base + row) * PROJ + jcol) = ov;
        }
        __syncwarp();

        xv = xn; chunk = next; valid = nvalid;
    }
}

extern "C" void kernel_launch(void* const* d_in, const int* in_sizes, int n_in,
                              void* d_out, int out_size)
{
    const float* x       = (const float*)d_in[0];
    const float* weights = (const float*)d_in[1];
    const float* W       = (const float*)d_in[2];
    const float* b       = (const float*)d_in[3];
    const float* gamma   = (const float*)d_in[4];
    const float* beta    = (const float*)d_in[5];
    float* out = (float*)d_out;
    int Bn = in_sizes[0] / NQ;

    quantum_kernel<<<GRID, TPB>>>(x, weights, W, b, gamma, beta, out, Bn);
}